// round 3
// baseline (speedup 1.0000x reference)
#include <cuda_runtime.h>
#include <cuda_bf16.h>

#define LDIM 4096
#define BDIM 32
#define CIN  64
#define ODIM 128
#define KDIM 9
#define CCHUNKS 4               // split-K chunks over channel dim
#define CPER   (CIN / CCHUNKS)  // 16 channels per chunk
#define OCHUNK 32               // outputs per main-kernel block

typedef unsigned long long u64;

// Scratch (allocation-free rule: __device__ globals)
__device__ float g_part[CCHUNKS * BDIM * LDIM]; // partial channel sums, 2 MB
__device__ float g_wcn[ODIM * KDIM];            // normalized weight_coeff
__device__ float g_evinv;                       // 1 / ||err_vector||

// ---- packed f32x2 helpers (Blackwell FFMA2 path) ----
__device__ __forceinline__ u64 pack2(float lo, float hi) {
    u64 r; asm("mov.b64 %0, {%1,%2};" : "=l"(r) : "f"(lo), "f"(hi)); return r;
}
__device__ __forceinline__ u64 ffma2(u64 a, u64 b, u64 c) {
    u64 d; asm("fma.rn.f32x2 %0, %1, %2, %3;" : "=l"(d) : "l"(a), "l"(b), "l"(c));
    return d;
}
__device__ __forceinline__ float2 unpack2(u64 v) {
    float2 f; asm("mov.b64 {%0,%1}, %2;" : "=f"(f.x), "=f"(f.y) : "l"(v)); return f;
}

// ---------------------------------------------------------------------------
// Kernel A: split-K channel reduction (512 blocks) + prep (block 512)
// ---------------------------------------------------------------------------
__global__ __launch_bounds__(256) void reduce_prep_kernel(
    const float* __restrict__ x,
    const float* __restrict__ wc,
    const float* __restrict__ ev) {

    const int bx = blockIdx.x;
    const int t  = threadIdx.x;

    if (bx < BDIM * 4 * CCHUNKS) {             // 512 reduce blocks
        const int b   = bx >> 4;               // 0..31
        const int sub = bx & 15;
        const int lt  = sub >> 2;              // l-tile 0..3
        const int cc  = sub & 3;               // channel chunk 0..3
        const int l4  = lt * 256 + t;          // 0..1023

        const float4* xp = reinterpret_cast<const float4*>(x) +
                           ((size_t)b * CIN + cc * CPER) * (LDIM / 4) + l4;
        float4 a0 = make_float4(0.f, 0.f, 0.f, 0.f);
        float4 a1 = make_float4(0.f, 0.f, 0.f, 0.f);
#pragma unroll
        for (int i = 0; i < CPER; i += 2) {
            float4 v0 = __ldg(xp + (i    ) * (LDIM / 4));
            float4 v1 = __ldg(xp + (i + 1) * (LDIM / 4));
            a0.x += v0.x; a0.y += v0.y; a0.z += v0.z; a0.w += v0.w;
            a1.x += v1.x; a1.y += v1.y; a1.z += v1.z; a1.w += v1.w;
        }
        a0.x += a1.x; a0.y += a1.y; a0.z += a1.z; a0.w += a1.w;
        reinterpret_cast<float4*>(g_part)[(cc * BDIM + b) * (LDIM / 4) + l4] = a0;
        return;
    }

    // ---- prep block ----
    __shared__ float red[256];
    float ssq = 0.f;
    for (int i = t; i < LDIM; i += 256) { float v = ev[i]; ssq += v * v; }
    red[t] = ssq;
    __syncthreads();
    for (int s = 128; s > 0; s >>= 1) {
        if (t < s) red[t] += red[t + s];
        __syncthreads();
    }
    if (t == 0) g_evinv = rsqrtf(red[0]);

    if (t < ODIM) {
        float w[KDIM];
        float n = 0.f;
#pragma unroll
        for (int k = 0; k < KDIM; ++k) { w[k] = wc[t * KDIM + k]; n += w[k] * w[k]; }
        float inv = rsqrtf(n);
#pragma unroll
        for (int k = 0; k < KDIM; ++k) g_wcn[t * KDIM + k] = w[k] * inv;
    }
}

// ---------------------------------------------------------------------------
// Kernel B: out[b,o,l] = ev[l]/||ev|| * sum_k wcn[o,k]*xs[b, idx[k,l]] + bias[o]
// grid: (4 l-tiles, 32 b, 4 o-chunks of 32) = 512 blocks, 256 threads.
// Packed-f32x2 FFMA inner loop; weights pre-duplicated {w,w} in smem with
// bias in slot 9 so each o needs only LDS.128-pair loads.
// ---------------------------------------------------------------------------
__global__ __launch_bounds__(256) void gmconv_main_kernel(
    const int*   __restrict__ idxm,
    const float* __restrict__ ev,
    const float* __restrict__ bias,
    float*       __restrict__ out) {

    __shared__ float s_xs[LDIM];               // 16 KB
    __shared__ u64   s_wcp[OCHUNK * 12];       // {w,w} x9, {bias,bias}, pad; 3 KB

    const int tile  = blockIdx.x;              // 0..3
    const int b     = blockIdx.y;              // 0..31
    const int obase = blockIdx.z * OCHUNK;     // 0,32,64,96
    const int t     = threadIdx.x;

    // stage xs[b] = sum of 4 split-K partials (L2-resident)
    {
        float4* s4 = reinterpret_cast<float4*>(s_xs);
        const float4* g4 = reinterpret_cast<const float4*>(g_part);
        for (int i = t; i < LDIM / 4; i += 256) {
            float4 a = __ldg(&g4[(0 * BDIM + b) * (LDIM / 4) + i]);
            float4 c = __ldg(&g4[(1 * BDIM + b) * (LDIM / 4) + i]);
            float4 d = __ldg(&g4[(2 * BDIM + b) * (LDIM / 4) + i]);
            float4 e = __ldg(&g4[(3 * BDIM + b) * (LDIM / 4) + i]);
            s4[i] = make_float4(a.x + c.x + d.x + e.x, a.y + c.y + d.y + e.y,
                                a.z + c.z + d.z + e.z, a.w + c.w + d.w + e.w);
        }
        // packed weights + bias
        for (int i = t; i < OCHUNK * 12; i += 256) {
            int o = i / 12, s = i - o * 12;
            float w = (s < KDIM) ? g_wcn[(obase + o) * KDIM + s]
                                 : (s == KDIM ? bias[obase + o] : 0.f);
            s_wcp[i] = pack2(w, w);
        }
    }
    __syncthreads();

    const int l = tile * 1024 + t * 4;
    const float evinv = g_evinv;
    float4 e4 = __ldg(reinterpret_cast<const float4*>(ev + l));
    const float ex = e4.x * evinv, ey = e4.y * evinv,
                ez = e4.z * evinv, ew = e4.w * evinv;

    // gather 9 neighbors per lane from smem, pre-scaled, packed into f32x2
    u64 g01[KDIM], g23[KDIM];
#pragma unroll
    for (int k = 0; k < KDIM; ++k) {
        int4 id = __ldg(reinterpret_cast<const int4*>(idxm + k * LDIM + l));
        g01[k] = pack2(s_xs[id.x] * ex, s_xs[id.y] * ey);
        g23[k] = pack2(s_xs[id.z] * ez, s_xs[id.w] * ew);
    }

    float* outp = out + ((size_t)b * ODIM + obase) * LDIM + l;
#pragma unroll 2
    for (int o = 0; o < OCHUNK; ++o) {
        const u64* wp = &s_wcp[o * 12];
        u64 acc01 = wp[9];                     // {bias,bias}
        u64 acc23 = wp[9];
#pragma unroll
        for (int k = 0; k < KDIM; ++k) {
            const u64 w2 = wp[k];              // LDS broadcast, pair-vectorizable
            acc01 = ffma2(w2, g01[k], acc01);
            acc23 = ffma2(w2, g23[k], acc23);
        }
        float2 r01 = unpack2(acc01);
        float2 r23 = unpack2(acc23);
        *reinterpret_cast<float4*>(outp + (size_t)o * LDIM) =
            make_float4(r01.x, r01.y, r23.x, r23.y);  // stays in L2 (fits)
    }
}

// ---------------------------------------------------------------------------
extern "C" void kernel_launch(void* const* d_in, const int* in_sizes, int n_in,
                              void* d_out, int out_size) {
    const float* x    = nullptr;
    const float* wc   = nullptr;
    const float* ev   = nullptr;
    const float* bias = nullptr;
    const int*   idxm = nullptr;

    for (int i = 0; i < n_in; ++i) {
        switch (in_sizes[i]) {
            case BDIM * CIN * LDIM: x    = (const float*)d_in[i]; break;  // 8388608
            case ODIM * KDIM:       wc   = (const float*)d_in[i]; break;  // 1152
            case LDIM:              ev   = (const float*)d_in[i]; break;  // 4096
            case ODIM:              bias = (const float*)d_in[i]; break;  // 128
            case KDIM * LDIM:       idxm = (const int*)  d_in[i]; break;  // 36864
            default: break;
        }
    }

    float* out = (float*)d_out;

    reduce_prep_kernel<<<BDIM * 4 * CCHUNKS + 1, 256>>>(x, wc, ev);
    gmconv_main_kernel<<<dim3(4, BDIM, 4), 256>>>(idxm, ev, bias, out);
}

// round 4
// speedup vs baseline: 1.3012x; 1.3012x over previous
#include <cuda_runtime.h>
#include <cuda_bf16.h>

#define LDIM 4096
#define BDIM 32
#define CIN  64
#define ODIM 128
#define KDIM 9
#define CCHUNKS 2               // split-K chunks over channel dim
#define CPER   (CIN / CCHUNKS)  // 32 channels per chunk
#define OCHUNK 64               // outputs per main-kernel block
#define WSTRIDE 12              // padded weight row: w0..w8, bias, pad, pad

// Scratch (allocation-free rule: __device__ globals)
__device__ float g_part[CCHUNKS * BDIM * LDIM]; // partial channel sums, 1 MB
__device__ float g_wcn[ODIM * KDIM];            // normalized weight_coeff
__device__ float g_evinv;                       // 1 / ||err_vector||

// ---------------------------------------------------------------------------
// Kernel A: split-K channel reduction (512 blocks x 128 thr) + prep (block 512)
//   block bx<512: b = bx>>4, lt = (bx&15)>>1, cc = bx&1
//   g_part[cc][b][lt*512 .. +512) = sum over 32 channels
// ---------------------------------------------------------------------------
__global__ __launch_bounds__(128) void reduce_prep_kernel(
    const float* __restrict__ x,
    const float* __restrict__ wc,
    const float* __restrict__ ev) {

    const int bx = blockIdx.x;
    const int t  = threadIdx.x;

    if (bx < BDIM * 16) {                      // 512 reduce blocks
        const int b   = bx >> 4;               // 0..31
        const int sub = bx & 15;
        const int lt  = sub >> 1;              // l-tile 0..7 (128 float4 each)
        const int cc  = sub & 1;               // channel chunk 0..1
        const int l4  = lt * 128 + t;          // 0..1023

        const float4* xp = reinterpret_cast<const float4*>(x) +
                           ((size_t)b * CIN + cc * CPER) * (LDIM / 4) + l4;
        float4 a0 = make_float4(0.f, 0.f, 0.f, 0.f);
        float4 a1 = make_float4(0.f, 0.f, 0.f, 0.f);
#pragma unroll 8
        for (int i = 0; i < CPER; i += 2) {
            float4 v0 = __ldg(xp + (i    ) * (LDIM / 4));
            float4 v1 = __ldg(xp + (i + 1) * (LDIM / 4));
            a0.x += v0.x; a0.y += v0.y; a0.z += v0.z; a0.w += v0.w;
            a1.x += v1.x; a1.y += v1.y; a1.z += v1.z; a1.w += v1.w;
        }
        a0.x += a1.x; a0.y += a1.y; a0.z += a1.z; a0.w += a1.w;
        reinterpret_cast<float4*>(g_part)[(cc * BDIM + b) * (LDIM / 4) + l4] = a0;
        return;
    }

    // ---- prep block (128 threads) ----
    __shared__ float red[128];
    float ssq = 0.f;
    for (int i = t; i < LDIM; i += 128) { float v = ev[i]; ssq += v * v; }
    red[t] = ssq;
    __syncthreads();
    for (int s = 64; s > 0; s >>= 1) {
        if (t < s) red[t] += red[t + s];
        __syncthreads();
    }
    if (t == 0) g_evinv = rsqrtf(red[0]);

    // one thread per output channel (128 threads = ODIM)
    {
        float w[KDIM];
        float n = 0.f;
#pragma unroll
        for (int k = 0; k < KDIM; ++k) { w[k] = wc[t * KDIM + k]; n += w[k] * w[k]; }
        float inv = rsqrtf(n);
#pragma unroll
        for (int k = 0; k < KDIM; ++k) g_wcn[t * KDIM + k] = w[k] * inv;
    }
}

// ---------------------------------------------------------------------------
// Kernel B: out[b,o,l] = ev[l]/||ev|| * sum_k wcn[o,k]*xs[b, idx[k,l]] + bias[o]
// grid: (8 l-tiles of 512, 32 b, 2 o-chunks of 64) = 512 blocks x 128 thr.
// Scalar FMA; weights+bias in padded 12-float rows -> 2x LDS.128 + 1x LDS.64.
// ---------------------------------------------------------------------------
__global__ __launch_bounds__(128) void gmconv_main_kernel(
    const int*   __restrict__ idxm,
    const float* __restrict__ ev,
    const float* __restrict__ bias,
    float*       __restrict__ out) {

    __shared__ float s_xs[LDIM];                    // 16 KB
    __shared__ float s_w[OCHUNK * WSTRIDE];         // 3 KB: w0..8, bias, pad

    const int tile  = blockIdx.x;                   // 0..7
    const int b     = blockIdx.y;                   // 0..31
    const int obase = blockIdx.z * OCHUNK;          // 0, 64
    const int t     = threadIdx.x;

    // stage xs[b] = p0 + p1 (L2-resident partials)
    {
        float4* s4 = reinterpret_cast<float4*>(s_xs);
        const float4* g4 = reinterpret_cast<const float4*>(g_part);
#pragma unroll
        for (int i = t; i < LDIM / 4; i += 128) {
            float4 p0 = __ldg(&g4[(0 * BDIM + b) * (LDIM / 4) + i]);
            float4 p1 = __ldg(&g4[(1 * BDIM + b) * (LDIM / 4) + i]);
            s4[i] = make_float4(p0.x + p1.x, p0.y + p1.y,
                                p0.z + p1.z, p0.w + p1.w);
        }
        // padded weight rows
#pragma unroll
        for (int i = t; i < OCHUNK * WSTRIDE; i += 128) {
            int o = i / WSTRIDE, s = i - o * WSTRIDE;
            s_w[i] = (s < KDIM) ? g_wcn[(obase + o) * KDIM + s]
                                : (s == KDIM ? bias[obase + o] : 0.f);
        }
    }
    __syncthreads();

    const int l = tile * 512 + t * 4;
    const float evinv = g_evinv;
    float4 e4 = __ldg(reinterpret_cast<const float4*>(ev + l));
    const float ex = e4.x * evinv, ey = e4.y * evinv,
                ez = e4.z * evinv, ew = e4.w * evinv;

    // gather 9 neighbors per lane from smem, pre-scaled by ev[l]/||ev||
    float gx[KDIM], gy[KDIM], gz[KDIM], gw[KDIM];
#pragma unroll
    for (int k = 0; k < KDIM; ++k) {
        int4 id = __ldg(reinterpret_cast<const int4*>(idxm + k * LDIM + l));
        gx[k] = s_xs[id.x] * ex;
        gy[k] = s_xs[id.y] * ey;
        gz[k] = s_xs[id.z] * ez;
        gw[k] = s_xs[id.w] * ew;
    }

    float* outp = out + ((size_t)b * ODIM + obase) * LDIM + l;
#pragma unroll 2
    for (int o = 0; o < OCHUNK; ++o) {
        const float* wp = s_w + o * WSTRIDE;
        const float bo = wp[KDIM];               // bias
        float ax = bo, ay = bo, az = bo, aw = bo;
#pragma unroll
        for (int k = 0; k < KDIM; ++k) {
            const float w = wp[k];               // smem broadcast (vectorizable)
            ax = fmaf(w, gx[k], ax);
            ay = fmaf(w, gy[k], ay);
            az = fmaf(w, gz[k], az);
            aw = fmaf(w, gw[k], aw);
        }
        // streaming store: output never re-read; keep L2 for x/partials
        __stcs(reinterpret_cast<float4*>(outp + (size_t)o * LDIM),
               make_float4(ax, ay, az, aw));
    }
}

// ---------------------------------------------------------------------------
extern "C" void kernel_launch(void* const* d_in, const int* in_sizes, int n_in,
                              void* d_out, int out_size) {
    const float* x    = nullptr;
    const float* wc   = nullptr;
    const float* ev   = nullptr;
    const float* bias = nullptr;
    const int*   idxm = nullptr;

    for (int i = 0; i < n_in; ++i) {
        switch (in_sizes[i]) {
            case BDIM * CIN * LDIM: x    = (const float*)d_in[i]; break;  // 8388608
            case ODIM * KDIM:       wc   = (const float*)d_in[i]; break;  // 1152
            case LDIM:              ev   = (const float*)d_in[i]; break;  // 4096
            case ODIM:              bias = (const float*)d_in[i]; break;  // 128
            case KDIM * LDIM:       idxm = (const int*)  d_in[i]; break;  // 36864
            default: break;
        }
    }

    float* out = (float*)d_out;

    reduce_prep_kernel<<<BDIM * 16 + 1, 128>>>(x, wc, ev);
    gmconv_main_kernel<<<dim3(8, BDIM, 2), 128>>>(idxm, ev, bias, out);
}